// round 1
// baseline (speedup 1.0000x reference)
#include <cuda_runtime.h>
#include <math.h>

#define NB 512
#define ND 512
#define EPSF 1e-6f

// ---------------- scratch (__device__ globals; no allocation allowed) ----------------
__device__ float g_n1[NB * ND];
__device__ float g_n2[NB * ND];
__device__ float g_sim[NB * NB];
__device__ float g_sim2[NB * NB];
__device__ float g_ld1[NB], g_ld2[NB];
__device__ float g_sq1[NB], g_sq2[NB];
__device__ float g_ms1[NB], g_ms2[NB];
__device__ float g_lse_row[NB], g_lse_col[NB], g_diagl[NB], g_u[NB];

// ---------------- reduction helpers ----------------
__device__ __forceinline__ float wsum(float v) {
#pragma unroll
    for (int o = 16; o; o >>= 1) v += __shfl_down_sync(0xffffffffu, v, o);
    return v;
}
__device__ __forceinline__ float wmax(float v) {
#pragma unroll
    for (int o = 16; o; o >>= 1) v = fmaxf(v, __shfl_down_sync(0xffffffffu, v, o));
    return v;
}

// ---------------- kernel 1: per-row normalize + stats ----------------
// grid = 2*NB blocks, 256 threads. Blocks [0,NB) handle (mu1, s1), rest (mu2, s2).
__global__ void prep_kernel(const float* __restrict__ mu1, const float* __restrict__ s1,
                            const float* __restrict__ mu2, const float* __restrict__ s2)
{
    __shared__ float sh[3][8];
    __shared__ float s_inv;
    const int row = blockIdx.x;
    const bool first = row < NB;
    const int r = first ? row : row - NB;
    const float* mu = (first ? mu1 : mu2) + r * ND;
    const float* sg = (first ? s1 : s2) + r * ND;
    float* nout = (first ? g_n1 : g_n2) + r * ND;
    const int t = threadIdx.x;

    float ssq = 0.f, lsum = 0.f, msum = 0.f;
    for (int c = t; c < ND; c += 256) {
        float x = mu[c];
        ssq += x * x;
        float sv = sg[c];
        lsum += __logf(sv + EPSF);
        msum += sv;
    }
    ssq = wsum(ssq); lsum = wsum(lsum); msum = wsum(msum);
    const int lane = t & 31, w = t >> 5;
    if (!lane) { sh[0][w] = ssq; sh[1][w] = lsum; sh[2][w] = msum; }
    __syncthreads();
    if (t == 0) {
        float a = 0.f, b = 0.f, c2 = 0.f;
        for (int k = 0; k < 8; k++) { a += sh[0][k]; b += sh[1][k]; c2 += sh[2][k]; }
        float inv = 1.0f / fmaxf(sqrtf(a), 1e-12f);
        s_inv = inv;
        (first ? g_ld1 : g_ld2)[r] = b;
        (first ? g_ms1 : g_ms2)[r] = c2 * (1.0f / ND);
        (first ? g_sq1 : g_sq2)[r] = a * inv * inv;   // == sum(n^2), ~1.0
    }
    __syncthreads();
    const float inv = s_inv;
    for (int c = t; c < ND; c += 256) nout[c] = mu[c] * inv;
}

// ---------------- kernel 2: the O(B^2 D) Bhattacharyya pass ----------------
#define BI 32
#define BJ 32
#define DC 32

__global__ void __launch_bounds__(256) bd_kernel(const float* __restrict__ s1g,
                                                 const float* __restrict__ s2g)
{
    // tiles stored [d][row] so the 32 tile rows for a fixed d are contiguous
    __shared__ float sn1[DC][BI + 1], ss1[DC][BI + 1];
    __shared__ float sn2[DC][BJ + 1], ss2[DC][BJ + 1];

    const int bi = blockIdx.y * BI, bj = blockIdx.x * BJ;
    const int tid = threadIdx.x;
    const int tx = tid & 15, ty = tid >> 4;    // 16x16 threads, each 2x2 outputs
    const int i0 = 2 * ty, j0 = 2 * tx;
    const int lr = tid >> 5, lc = tid & 31;    // tile loader mapping

    float t1[2][2]   = {{0.f, 0.f}, {0.f, 0.f}};
    float ldacc[2][2] = {{0.f, 0.f}, {0.f, 0.f}};
    float dot[2][2]  = {{0.f, 0.f}, {0.f, 0.f}};

    for (int dc = 0; dc < ND; dc += DC) {
#pragma unroll
        for (int k = 0; k < 4; k++) {
            const int r = k * 8 + lr;
            sn1[lc][r] = g_n1[(bi + r) * ND + dc + lc];
            ss1[lc][r] = fmaf(0.5f, s1g[(bi + r) * ND + dc + lc], 0.5f * EPSF);
            sn2[lc][r] = g_n2[(bj + r) * ND + dc + lc];
            ss2[lc][r] = fmaf(0.5f, s2g[(bj + r) * ND + dc + lc], 0.5f * EPSF);
        }
        __syncthreads();

#pragma unroll
        for (int du = 0; du < DC; du += 4) {
            // batch log over products of 4: worst case (1e-6)^4 = 1e-24 > FLT_MIN
            float prod[2][2] = {{1.f, 1.f}, {1.f, 1.f}};
#pragma unroll
            for (int dd = 0; dd < 4; dd++) {
                const int d = du + dd;
                const float a0 = sn1[d][i0], a1 = sn1[d][i0 + 1];
                const float p0 = ss1[d][i0], p1 = ss1[d][i0 + 1];
                const float b0 = sn2[d][j0], b1 = sn2[d][j0 + 1];
                const float q0 = ss2[d][j0], q1 = ss2[d][j0 + 1];
#pragma unroll
                for (int x = 0; x < 2; x++) {
                    const float a = x ? a1 : a0;
                    const float p = x ? p1 : p0;
#pragma unroll
                    for (int y = 0; y < 2; y++) {
                        const float b = y ? b1 : b0;
                        const float q = y ? q1 : q0;
                        const float s = p + q;                 // = 0.5*(s1+s2)+EPS
                        float rr;
                        asm("rcp.approx.f32 %0, %1;" : "=f"(rr) : "f"(s));
                        const float diff = a - b;
                        t1[x][y] = fmaf(diff * rr, diff, t1[x][y]);
                        prod[x][y] *= s;
                        dot[x][y] = fmaf(a, b, dot[x][y]);
                    }
                }
            }
#pragma unroll
            for (int x = 0; x < 2; x++)
#pragma unroll
                for (int y = 0; y < 2; y++)
                    ldacc[x][y] += __logf(prod[x][y]);
        }
        __syncthreads();
    }

    // epilogue: sim = exp(-bd/D), sim2 = exp(-(sq1+sq2-2*dot))
#pragma unroll
    for (int x = 0; x < 2; x++) {
        const int i = bi + i0 + x;
        const float ld1 = g_ld1[i], sq1 = g_sq1[i];
#pragma unroll
        for (int y = 0; y < 2; y++) {
            const int j = bj + j0 + y;
            const float term2 = ldacc[x][y] - 0.5f * (ld1 + g_ld2[j]);
            const float bd = fmaf(0.125f, t1[x][y], 0.5f * term2);
            g_sim[i * NB + j]  = __expf(-bd * (1.0f / ND));
            g_sim2[i * NB + j] = __expf(fmaf(2.0f, dot[x][y], -(sq1 + g_sq2[j])));
        }
    }
}

// ---------------- kernel 3: row LSE + uncertainty ----------------
// grid = NB blocks, 256 threads (each thread handles cols t and t+256)
__global__ void row_kernel(const float* __restrict__ lsp)
{
    __shared__ float shm[8], shm2[8], shs[8];
    __shared__ float s_diag, s_diag2, s_M, s_M2;
    const int i = blockIdx.x;
    const int t = threadIdx.x;
    const float scale = lsp[0];
    const float* simr = g_sim + i * NB;
    const float* sim2r = g_sim2 + i * NB;

    const float l0 = scale * simr[t],       l1 = scale * simr[t + 256];
    const float v0 = sim2r[t],              v1 = sim2r[t + 256];
    float m = fmaxf(l0, l1);
    float m2 = -1.0f;                       // sim2 > 0 always
    if (t == i)       { s_diag = l0; s_diag2 = v0; } else m2 = v0;
    if (t + 256 == i) { s_diag = l1; s_diag2 = v1; } else m2 = fmaxf(m2, v1);

    m = wmax(m); m2 = wmax(m2);
    const int lane = t & 31, w = t >> 5;
    if (!lane) { shm[w] = m; shm2[w] = m2; }
    __syncthreads();
    if (t == 0) {
        float M = shm[0], M2 = shm2[0];
        for (int k = 1; k < 8; k++) { M = fmaxf(M, shm[k]); M2 = fmaxf(M2, shm2[k]); }
        s_M = M; s_M2 = M2;
    }
    __syncthreads();
    const float M = s_M;
    float su = __expf(l0 - M) + __expf(l1 - M);
    su = wsum(su);
    if (!lane) shs[w] = su;
    __syncthreads();
    if (t == 0) {
        float S = 0.f;
        for (int k = 0; k < 8; k++) S += shs[k];
        g_lse_row[i] = M + __logf(S);
        g_diagl[i]   = s_diag;
        g_u[i]       = __expf(-s_diag2 / s_M2);
    }
}

// ---------------- kernel 4: column LSE (online softmax, coalesced) ----------------
// grid = NB/32 blocks, 256 threads: x = col-in-group, y = row-stripe
__global__ void col_kernel(const float* __restrict__ lsp)
{
    __shared__ float sm[8][32], ss[8][32];
    const float scale = lsp[0];
    const int x = threadIdx.x & 31, y = threadIdx.x >> 5;
    const int j = blockIdx.x * 32 + x;
    float m = -1e30f, s = 0.0f;
    for (int r = y; r < NB; r += 8) {
        const float l = scale * g_sim[r * NB + j];
        const float nm = fmaxf(m, l);
        s = s * __expf(m - nm) + __expf(l - nm);
        m = nm;
    }
    sm[y][x] = m; ss[y][x] = s;
    __syncthreads();
    if (y == 0) {
        float M = m;
        for (int k = 1; k < 8; k++) M = fmaxf(M, sm[k][x]);
        float S = 0.f;
        for (int k = 0; k < 8; k++) S += ss[k][x] * __expf(sm[k][x] - M);
        g_lse_col[j] = M + __logf(S);
    }
}

// ---------------- kernel 5: final scalar reductions ----------------
__global__ void final_kernel(float* __restrict__ out)
{
    __shared__ float sh[6][16];
    const int t = threadIdx.x;   // 512 threads
    const float ce_r = g_lse_row[t] - g_diagl[t];
    const float ce_c = g_lse_col[t] - g_diagl[t];
    const float u = g_u[t];
    const float as = 0.5f * (g_ms1[t] + g_ms2[t]);
    float v[6] = { ce_r, ce_c, u, u * u, as * as, u * as };
    const int lane = t & 31, w = t >> 5;
#pragma unroll
    for (int k = 0; k < 6; k++) {
        const float r = wsum(v[k]);
        if (!lane) sh[k][w] = r;
    }
    __syncthreads();
    if (t == 0) {
        float s[6];
        for (int k = 0; k < 6; k++) {
            float a = 0.f;
            for (int q = 0; q < 16; q++) a += sh[k][q];
            s[k] = a;
        }
        const float loss_pro = 0.5f * ((s[0] + s[1]) * (1.0f / NB));
        const float cosv = s[5] / (fmaxf(sqrtf(s[3]), 1e-12f) * fmaxf(sqrtf(s[4]), 1e-12f));
        out[0] = loss_pro;
        out[1] = 2.4f * (1.0f - cosv);
        out[2] = 0.5f * (s[2] * (1.0f / NB));
    }
}

// ---------------- launch ----------------
extern "C" void kernel_launch(void* const* d_in, const int* in_sizes, int n_in,
                              void* d_out, int out_size)
{
    const float* mu1 = (const float*)d_in[0];
    const float* s1  = (const float*)d_in[1];
    const float* mu2 = (const float*)d_in[2];
    const float* s2  = (const float*)d_in[3];
    const float* ls  = (const float*)d_in[4];
    float* out = (float*)d_out;

    prep_kernel<<<2 * NB, 256>>>(mu1, s1, mu2, s2);
    dim3 grid(NB / BJ, NB / BI);
    bd_kernel<<<grid, 256>>>(s1, s2);
    row_kernel<<<NB, 256>>>(ls);
    col_kernel<<<NB / 32, 256>>>(ls);
    final_kernel<<<1, NB>>>(out);
}